// round 7
// baseline (speedup 1.0000x reference)
#include <cuda_runtime.h>
#include <cstdint>

// ParabolicPool2D: out[b,c,i,j] = max_{p,q in 0..2} f[b,c,2i+p,2j+q] + h[c,p,q]
// h[c,p,q] = -t[c]*(zp^2+zq^2)/2 -> separable with s = t[c]/2:
//   colmax[r][j] = max(f[r][2j]-s, f[r][2j+1], f[r][2j+2]-s)
//   out[i][j]    = max(colmax[2i]-s, colmax[2i+1], colmax[2i+2]-s)
//
// Persistent double-buffered pipeline: 456 blocks (152 SMs x 3 resident, one
// wave). Each block owns ~36 contiguous (image, 16-row) tiles. Two 33KB smem
// stages; cp.async.bulk of tile k+2 is issued as soon as tile k's compute
// drains, so every block keeps a 33KB sequential DRAM burst in flight
// continuously. Compute: 8 warps x 2 output rows from smem.

#define Wd 256
#define OWd 127
#define OHd 127

#define NB 456                     // 152 SMs * 3 blocks
#define TOTAL_TILES 16384          // 2048 images * 8 tiles
#define STAGE_FLOATS (33 * Wd)     // 8448 floats = 33792 B
#define SMEM_BYTES (2 * STAGE_FLOATS * 4 + 16)

__device__ __forceinline__ uint32_t smem_u32(const void* p) {
    return (uint32_t)__cvta_generic_to_shared(p);
}

__device__ __forceinline__ void mbar_wait(uint32_t mb, uint32_t parity) {
    asm volatile(
        "{\n\t.reg .pred P;\n\t"
        "W_%=:\n\t"
        "mbarrier.try_wait.parity.acquire.cta.shared::cta.b64 P, [%0], %1, 0x989680;\n\t"
        "@P bra.uni D_%=;\n\t"
        "bra.uni W_%=;\n\t"
        "D_%=:\n\t}"
        :: "r"(mb), "r"(parity) : "memory");
}

__device__ __forceinline__ void issue_tile(const float* __restrict__ f,
                                           int tt, uint32_t dst, uint32_t mb) {
    int img = tt >> 3;
    int i0  = (tt & 7) << 4;
    int nout = min(16, OHd - i0);
    int bytes = (2 * nout + 1) * (Wd * 4);          // 33792 or 31744
    const float* src = f + (size_t)img * (256 * Wd) + (size_t)(i0 << 1) * Wd;
    asm volatile("mbarrier.arrive.expect_tx.shared.b64 _, [%0], %1;"
                 :: "r"(mb), "r"(bytes) : "memory");
    asm volatile("cp.async.bulk.shared::cta.global.mbarrier::complete_tx::bytes"
                 " [%0], [%1], %2, [%3];"
                 :: "r"(dst), "l"(src), "r"(bytes), "r"(mb) : "memory");
}

__device__ __forceinline__ void cm_row(const float* __restrict__ sr, int lane,
                                       float s, float cm[4]) {
    float4 a = *(const float4*)(sr + 4 * lane);
    float4 b = *(const float4*)(sr + 4 * lane + 128);
    float n0 = sr[4 * lane + 4];                          // col 4L+4
    float n1 = sr[(lane == 31) ? 255 : (4 * lane + 132)]; // col 4L+132 (lane31 unused)
    cm[0] = fmaxf(fmaxf(a.x - s, a.y), a.z - s);          // out col 2L
    cm[1] = fmaxf(fmaxf(a.z - s, a.w), n0 - s);           // out col 2L+1
    cm[2] = fmaxf(fmaxf(b.x - s, b.y), b.z - s);          // out col 2L+64
    cm[3] = fmaxf(fmaxf(b.z - s, b.w), n1 - s);           // out col 2L+65
}

__global__ void __launch_bounds__(256)
parabolic_pool2d_kernel(const float* __restrict__ f,
                        const float* __restrict__ t,
                        float* __restrict__ out) {
    extern __shared__ __align__(128) float sm[];          // 2 stages + mbars
    unsigned long long* mbar = (unsigned long long*)(sm + 2 * STAGE_FLOATS);

    int tid  = threadIdx.x;
    int w    = tid >> 5;
    int lane = tid & 31;
    int j0   = 2 * lane;
    bool lastlane = (lane == 31);

    long t0 = ((long)blockIdx.x * TOTAL_TILES) / NB;
    long t1 = ((long)(blockIdx.x + 1) * TOTAL_TILES) / NB;
    int ntiles = (int)(t1 - t0);

    uint32_t mb0 = smem_u32(&mbar[0]);
    uint32_t mb1 = smem_u32(&mbar[1]);
    uint32_t st0 = smem_u32(sm);
    uint32_t st1 = smem_u32(sm + STAGE_FLOATS);

    if (tid == 0) {
        asm volatile("mbarrier.init.shared.b64 [%0], 1;" :: "r"(mb0) : "memory");
        asm volatile("mbarrier.init.shared.b64 [%0], 1;" :: "r"(mb1) : "memory");
    }
    __syncthreads();
    if (tid == 0) {
        issue_tile(f, (int)t0, st0, mb0);
        if (ntiles > 1) issue_tile(f, (int)t0 + 1, st1, mb1);
    }

    for (int k = 0; k < ntiles; k++) {
        int sidx = k & 1;
        mbar_wait(sidx ? mb1 : mb0, (uint32_t)((k >> 1) & 1));

        int tt  = (int)t0 + k;
        int img = tt >> 3;
        int i0  = (tt & 7) << 4;
        int nout = min(16, OHd - i0);
        const float* buf = sm + (size_t)sidx * STAGE_FLOATS;
        float s = 0.5f * __ldg(t + (img & 127));
        float* op = out + (size_t)img * (OHd * OWd);

#pragma unroll
        for (int half = 0; half < 2; half++) {
            int i = w + 8 * half;                     // local output row 0..15
            if (i < nout) {
                const float* r0p = buf + (size_t)(2 * i) * Wd;
                float cmA[4], cmB[4], cmC[4];
                cm_row(r0p,          lane, s, cmA);
                cm_row(r0p + Wd,     lane, s, cmB);
                cm_row(r0p + 2 * Wd, lane, s, cmC);

                float o0 = fmaxf(fmaxf(cmA[0] - s, cmB[0]), cmC[0] - s);
                float o1 = fmaxf(fmaxf(cmA[1] - s, cmB[1]), cmC[1] - s);
                float o2 = fmaxf(fmaxf(cmA[2] - s, cmB[2]), cmC[2] - s);
                float o3 = fmaxf(fmaxf(cmA[3] - s, cmB[3]), cmC[3] - s);

                float* orow = op + (size_t)(i0 + i) * OWd;
                __stcs(orow + j0, o0);
                __stcs(orow + j0 + 1, o1);
                __stcs(orow + j0 + 64, o2);
                if (!lastlane) __stcs(orow + j0 + 65, o3);
            }
        }
        __syncthreads();                              // all warps done with buf
        if (tid == 0 && k + 2 < ntiles)
            issue_tile(f, tt + 2, sidx ? st1 : st0, sidx ? mb1 : mb0);
    }
}

extern "C" void kernel_launch(void* const* d_in, const int* in_sizes, int n_in,
                              void* d_out, int out_size) {
    const float* f = (const float*)d_in[0];   // [16,128,256,256] fp32
    const float* t = (const float*)d_in[1];   // [128] fp32
    float* out = (float*)d_out;               // [16,128,127,127] fp32
    static_assert(SMEM_BYTES <= 69632, "smem budget");
    cudaFuncSetAttribute(parabolic_pool2d_kernel,
                         cudaFuncAttributeMaxDynamicSharedMemorySize, SMEM_BYTES);
    parabolic_pool2d_kernel<<<NB, 256, SMEM_BYTES>>>(f, t, out);
}

// round 8
// speedup vs baseline: 1.0737x; 1.0737x over previous
#include <cuda_runtime.h>
#include <cstdint>

// ParabolicPool2D: out[b,c,i,j] = max_{p,q in 0..2} f[b,c,2i+p,2j+q] + h[c,p,q]
// h[c,p,q] = -t[c]*(zp^2+zq^2)/2 -> separable with s = t[c]/2:
//   colmax[r][j] = max(f[r][2j]-s, f[r][2j+1], f[r][2j+2]-s)
//   out[i][j]    = max(colmax[2i]-s, colmax[2i+1], colmax[2i+2]-s)
//
// Block = one (image, 16-output-row tile); bulk-load tile into smem as TWO
// halves (rows 0..16, rows 17..32) with separate mbarriers. Warp w computes
// output row w after half A lands (overlapping half B's flight), then row w+8
// after half B. Same 33.8KB smem -> 6 blocks/SM; sequential 17KB/16KB DRAM
// bursts keep row-buffer locality.

#define Wd 256
#define OWd 127
#define OHd 127

__device__ __forceinline__ uint32_t smem_u32(const void* p) {
    return (uint32_t)__cvta_generic_to_shared(p);
}

__device__ __forceinline__ void mbar_wait(uint32_t mb, uint32_t parity) {
    asm volatile(
        "{\n\t.reg .pred P;\n\t"
        "W_%=:\n\t"
        "mbarrier.try_wait.parity.acquire.cta.shared::cta.b64 P, [%0], %1, 0x989680;\n\t"
        "@P bra.uni D_%=;\n\t"
        "bra.uni W_%=;\n\t"
        "D_%=:\n\t}"
        :: "r"(mb), "r"(parity) : "memory");
}

__device__ __forceinline__ void cm_row(const float* __restrict__ sr, int lane,
                                       float s, float cm[4]) {
    float4 a = *(const float4*)(sr + 4 * lane);
    float4 b = *(const float4*)(sr + 4 * lane + 128);
    float n0 = sr[4 * lane + 4];                          // col 4L+4
    float n1 = sr[(lane == 31) ? 255 : (4 * lane + 132)]; // col 4L+132 (lane31 unused)
    cm[0] = fmaxf(fmaxf(a.x - s, a.y), a.z - s);          // out col 2L
    cm[1] = fmaxf(fmaxf(a.z - s, a.w), n0 - s);           // out col 2L+1
    cm[2] = fmaxf(fmaxf(b.x - s, b.y), b.z - s);          // out col 2L+64
    cm[3] = fmaxf(fmaxf(b.z - s, b.w), n1 - s);           // out col 2L+65
}

__device__ __forceinline__ void do_row(const float* __restrict__ buf, int i,
                                       float* __restrict__ op, int i0,
                                       int lane, int j0, bool lastlane, float s) {
    const float* r0p = buf + (size_t)(2 * i) * Wd;
    float cmA[4], cmB[4], cmC[4];
    cm_row(r0p,          lane, s, cmA);
    cm_row(r0p + Wd,     lane, s, cmB);
    cm_row(r0p + 2 * Wd, lane, s, cmC);

    float o0 = fmaxf(fmaxf(cmA[0] - s, cmB[0]), cmC[0] - s);
    float o1 = fmaxf(fmaxf(cmA[1] - s, cmB[1]), cmC[1] - s);
    float o2 = fmaxf(fmaxf(cmA[2] - s, cmB[2]), cmC[2] - s);
    float o3 = fmaxf(fmaxf(cmA[3] - s, cmB[3]), cmC[3] - s);

    float* orow = op + (size_t)(i0 + i) * OWd;
    __stcs(orow + j0, o0);
    __stcs(orow + j0 + 1, o1);
    __stcs(orow + j0 + 64, o2);
    if (!lastlane) __stcs(orow + j0 + 65, o3);
}

__global__ void __launch_bounds__(256)
parabolic_pool2d_kernel(const float* __restrict__ f,
                        const float* __restrict__ t,
                        float* __restrict__ out) {
    __shared__ __align__(128) float sm[33 * Wd];       // 33 input rows
    __shared__ __align__(8) unsigned long long mbar[2];

    int bid  = blockIdx.x;
    int img  = bid >> 3;                 // image = b*128 + c
    int tile = bid & 7;                  // 16-output-row tile within image
    int i0 = tile << 4;
    int nout = min(16, OHd - i0);        // 16, or 15 for tile 7
    int nin  = 2 * nout + 1;             // 33 or 31 input rows
    int bytesA = 17 * (Wd * 4);          // rows 0..16  (17408 B)
    int bytesB = (nin - 17) * (Wd * 4);  // rows 17..nin-1 (16384 or 14336 B)

    const float* src = f + (size_t)img * (256 * Wd) + (size_t)(i0 << 1) * Wd;

    uint32_t sm_a = smem_u32(sm);
    uint32_t mb0 = smem_u32(&mbar[0]);
    uint32_t mb1 = smem_u32(&mbar[1]);

    if (threadIdx.x == 0) {
        asm volatile("mbarrier.init.shared.b64 [%0], 1;" :: "r"(mb0) : "memory");
        asm volatile("mbarrier.init.shared.b64 [%0], 1;" :: "r"(mb1) : "memory");
    }
    __syncthreads();
    if (threadIdx.x == 0) {
        asm volatile("mbarrier.arrive.expect_tx.shared.b64 _, [%0], %1;"
                     :: "r"(mb0), "r"(bytesA) : "memory");
        asm volatile("cp.async.bulk.shared::cta.global.mbarrier::complete_tx::bytes"
                     " [%0], [%1], %2, [%3];"
                     :: "r"(sm_a), "l"(src), "r"(bytesA), "r"(mb0) : "memory");
        asm volatile("mbarrier.arrive.expect_tx.shared.b64 _, [%0], %1;"
                     :: "r"(mb1), "r"(bytesB) : "memory");
        asm volatile("cp.async.bulk.shared::cta.global.mbarrier::complete_tx::bytes"
                     " [%0], [%1], %2, [%3];"
                     :: "r"(sm_a + 17 * Wd * 4), "l"(src + 17 * Wd),
                        "r"(bytesB), "r"(mb1) : "memory");
    }

    float s = 0.5f * __ldg(t + (img & 127));
    float* op = out + (size_t)img * (OHd * OWd);
    int w    = threadIdx.x >> 5;
    int lane = threadIdx.x & 31;
    int j0   = 2 * lane;
    bool lastlane = (lane == 31);

    // first half: output rows 0..7 need input rows <= 16 (all in bulk A)
    mbar_wait(mb0, 0);
    do_row(sm, w, op, i0, lane, j0, lastlane, s);

    // second half: output rows 8..15 need input rows 16..32 (bulk A+B)
    mbar_wait(mb1, 0);
    int i = w + 8;
    if (i < nout)
        do_row(sm, i, op, i0, lane, j0, lastlane, s);
}

extern "C" void kernel_launch(void* const* d_in, const int* in_sizes, int n_in,
                              void* d_out, int out_size) {
    const float* f = (const float*)d_in[0];   // [16,128,256,256] fp32
    const float* t = (const float*)d_in[1];   // [128] fp32
    float* out = (float*)d_out;               // [16,128,127,127] fp32
    // 2048 images * 8 tiles = 16384 blocks, 256 threads each
    parabolic_pool2d_kernel<<<16384, 256>>>(f, t, out);
}

// round 9
// speedup vs baseline: 1.0765x; 1.0026x over previous
#include <cuda_runtime.h>
#include <cstdint>

// ParabolicPool2D: out[b,c,i,j] = max_{p,q in 0..2} f[b,c,2i+p,2j+q] + h[c,p,q]
// h[c,p,q] = -t[c]*(zp^2+zq^2)/2 -> separable with s = t[c]/2:
//   colmax[r][j] = max(f[r][2j]-s, f[r][2j+1], f[r][2j+2]-s)
//   out[i][j]    = max(colmax[2i]-s, colmax[2i+1], colmax[2i+2]-s)
//
// Block = one (image, 32-output-row tile): 65 input rows (66.6KB smem) loaded
// as 4 back-to-back cp.async.bulk chunks (17/16/16/16 rows) with separate
// mbarriers. Warp w computes output rows w and w+16, waiting only on the
// chunks it needs -> compute overlaps the remaining chunk flights. 512
// threads, 3 blocks/SM = 48 warps (same occupancy as the 16-row version) but
// seam re-reads drop 2.7% -> 1.2%.

#define Wd 256
#define OWd 127
#define OHd 127

#define STAGE_FLOATS (65 * Wd)                   // 16640 floats = 66560 B
#define SMEM_BYTES (STAGE_FLOATS * 4 + 32)       // + 4 mbarriers

__device__ __forceinline__ uint32_t smem_u32(const void* p) {
    return (uint32_t)__cvta_generic_to_shared(p);
}

__device__ __forceinline__ void mbar_wait(uint32_t mb, uint32_t parity) {
    asm volatile(
        "{\n\t.reg .pred P;\n\t"
        "W_%=:\n\t"
        "mbarrier.try_wait.parity.acquire.cta.shared::cta.b64 P, [%0], %1, 0x989680;\n\t"
        "@P bra.uni D_%=;\n\t"
        "bra.uni W_%=;\n\t"
        "D_%=:\n\t}"
        :: "r"(mb), "r"(parity) : "memory");
}

__device__ __forceinline__ void cm_row(const float* __restrict__ sr, int lane,
                                       float s, float cm[4]) {
    float4 a = *(const float4*)(sr + 4 * lane);
    float4 b = *(const float4*)(sr + 4 * lane + 128);
    // neighbor elements from lane+1 via shuffle (lane0 exports b.x to lane31)
    float h0 = (lane == 0) ? b.x : a.x;
    int src = (lane + 1) & 31;
    float n0 = __shfl_sync(0xffffffffu, h0, src);   // col 4L+4
    float n1 = __shfl_sync(0xffffffffu, b.x, src);  // col 4L+132 (lane31 unused)
    cm[0] = fmaxf(fmaxf(a.x - s, a.y), a.z - s);    // out col 2L
    cm[1] = fmaxf(fmaxf(a.z - s, a.w), n0 - s);     // out col 2L+1
    cm[2] = fmaxf(fmaxf(b.x - s, b.y), b.z - s);    // out col 2L+64
    cm[3] = fmaxf(fmaxf(b.z - s, b.w), n1 - s);     // out col 2L+65
}

__device__ __forceinline__ void do_row(const float* __restrict__ buf, int i,
                                       float* __restrict__ op, int i0,
                                       int lane, int j0, bool lastlane, float s) {
    const float* r0p = buf + (size_t)(2 * i) * Wd;
    float cmA[4], cmB[4], cmC[4];
    cm_row(r0p,          lane, s, cmA);
    cm_row(r0p + Wd,     lane, s, cmB);
    cm_row(r0p + 2 * Wd, lane, s, cmC);

    float o0 = fmaxf(fmaxf(cmA[0] - s, cmB[0]), cmC[0] - s);
    float o1 = fmaxf(fmaxf(cmA[1] - s, cmB[1]), cmC[1] - s);
    float o2 = fmaxf(fmaxf(cmA[2] - s, cmB[2]), cmC[2] - s);
    float o3 = fmaxf(fmaxf(cmA[3] - s, cmB[3]), cmC[3] - s);

    float* orow = op + (size_t)(i0 + i) * OWd;
    __stcs(orow + j0, o0);
    __stcs(orow + j0 + 1, o1);
    __stcs(orow + j0 + 64, o2);
    if (!lastlane) __stcs(orow + j0 + 65, o3);
}

__global__ void __launch_bounds__(512, 3)
parabolic_pool2d_kernel(const float* __restrict__ f,
                        const float* __restrict__ t,
                        float* __restrict__ out) {
    extern __shared__ __align__(128) float sm[];    // 65 input rows + mbars
    unsigned long long* mbar = (unsigned long long*)(sm + STAGE_FLOATS);

    int bid  = blockIdx.x;
    int img  = bid >> 2;                 // image = b*128 + c
    int tile = bid & 3;                  // 32-output-row tile within image
    int i0 = tile << 5;
    int nout = min(32, OHd - i0);        // 32, or 31 for tile 3
    int nin  = 2 * nout + 1;             // 65 or 63 input rows

    const float* src = f + (size_t)img * (256 * Wd) + (size_t)(i0 << 1) * Wd;

    // chunk row offsets / sizes: 0..16, 17..32, 33..48, 49..nin-1
    const int coff[4] = {0, 17, 33, 49};
    int csz[4];
    csz[0] = 17; csz[1] = 16; csz[2] = 16; csz[3] = nin - 49;   // 16 or 14

    uint32_t sm_a = smem_u32(sm);
    uint32_t mb[4];
#pragma unroll
    for (int q = 0; q < 4; q++) mb[q] = smem_u32(&mbar[q]);

    if (threadIdx.x == 0) {
#pragma unroll
        for (int q = 0; q < 4; q++)
            asm volatile("mbarrier.init.shared.b64 [%0], 1;" :: "r"(mb[q]) : "memory");
    }
    __syncthreads();
    if (threadIdx.x == 0) {
#pragma unroll
        for (int q = 0; q < 4; q++) {
            int bytes = csz[q] * (Wd * 4);
            asm volatile("mbarrier.arrive.expect_tx.shared.b64 _, [%0], %1;"
                         :: "r"(mb[q]), "r"(bytes) : "memory");
            asm volatile("cp.async.bulk.shared::cta.global.mbarrier::complete_tx::bytes"
                         " [%0], [%1], %2, [%3];"
                         :: "r"(sm_a + coff[q] * Wd * 4), "l"(src + coff[q] * Wd),
                            "r"(bytes), "r"(mb[q]) : "memory");
        }
    }

    float s = 0.5f * __ldg(t + (img & 127));
    float* op = out + (size_t)img * (OHd * OWd);
    int w    = threadIdx.x >> 5;         // 0..15
    int lane = threadIdx.x & 31;
    int j0   = 2 * lane;
    bool lastlane = (lane == 31);

    // phase 1: output row w (inputs 2w..2w+2, max 32)
    //   w<=7: chunk0 only; w>=8: chunk0+chunk1
    mbar_wait(mb[0], 0);
    if (w >= 8) mbar_wait(mb[1], 0);
    do_row(sm, w, op, i0, lane, j0, lastlane, s);

    // phase 2: output row w+16 (inputs 32..64)
    //   w<=7 (rows 16-23, inputs <=48): chunk1+chunk2
    //   w>=8 (rows 24-31, inputs <=64): chunk2+chunk3 (chunk1 already waited)
    if (w < 8) mbar_wait(mb[1], 0);
    mbar_wait(mb[2], 0);
    if (w >= 8) mbar_wait(mb[3], 0);
    int i = w + 16;
    if (i < nout)
        do_row(sm, i, op, i0, lane, j0, lastlane, s);
}

extern "C" void kernel_launch(void* const* d_in, const int* in_sizes, int n_in,
                              void* d_out, int out_size) {
    const float* f = (const float*)d_in[0];   // [16,128,256,256] fp32
    const float* t = (const float*)d_in[1];   // [128] fp32
    float* out = (float*)d_out;               // [16,128,127,127] fp32
    cudaFuncSetAttribute(parabolic_pool2d_kernel,
                         cudaFuncAttributeMaxDynamicSharedMemorySize, SMEM_BYTES);
    // 2048 images * 4 tiles = 8192 blocks, 512 threads each
    parabolic_pool2d_kernel<<<8192, 512, SMEM_BYTES>>>(f, t, out);
}

// round 10
// speedup vs baseline: 1.0804x; 1.0036x over previous
#include <cuda_runtime.h>
#include <cstdint>

// ParabolicPool2D: out[b,c,i,j] = max_{p,q in 0..2} f[b,c,2i+p,2j+q] + h[c,p,q]
// h[c,p,q] = -t[c]*(zp^2+zq^2)/2 -> separable with s = t[c]/2.
//
// Block = one (image, 16-output-row tile).
// Reads: tile's 33 input rows arrive as two cp.async.bulk chunks (17+16 rows)
//        -> long sequential DRAM read bursts; warp w computes row w after
//        chunk A, row w+8 after chunk B.
// Writes: results staged in smem (shifted by bo so smem==gmem mod 16), then
//        drained by ONE cp.async.bulk shared->global of the aligned middle
//        (8KB sequential burst) + <=3-float scalar head/tail.

#define Wd 256
#define OWd 127
#define OHd 127

#define OUTBUF 2040   // 3 (max shift) + 16*127 = 2035, padded

__device__ __forceinline__ uint32_t smem_u32(const void* p) {
    return (uint32_t)__cvta_generic_to_shared(p);
}

__device__ __forceinline__ void mbar_wait(uint32_t mb, uint32_t parity) {
    asm volatile(
        "{\n\t.reg .pred P;\n\t"
        "W_%=:\n\t"
        "mbarrier.try_wait.parity.acquire.cta.shared::cta.b64 P, [%0], %1, 0x989680;\n\t"
        "@P bra.uni D_%=;\n\t"
        "bra.uni W_%=;\n\t"
        "D_%=:\n\t}"
        :: "r"(mb), "r"(parity) : "memory");
}

__device__ __forceinline__ void cm_row(const float* __restrict__ sr, int lane,
                                       float s, float cm[4]) {
    float4 a = *(const float4*)(sr + 4 * lane);
    float4 b = *(const float4*)(sr + 4 * lane + 128);
    float h0 = (lane == 0) ? b.x : a.x;
    int src = (lane + 1) & 31;
    float n0 = __shfl_sync(0xffffffffu, h0, src);   // col 4L+4
    float n1 = __shfl_sync(0xffffffffu, b.x, src);  // col 4L+132 (lane31 unused)
    cm[0] = fmaxf(fmaxf(a.x - s, a.y), a.z - s);    // out col 2L
    cm[1] = fmaxf(fmaxf(a.z - s, a.w), n0 - s);     // out col 2L+1
    cm[2] = fmaxf(fmaxf(b.x - s, b.y), b.z - s);    // out col 2L+64
    cm[3] = fmaxf(fmaxf(b.z - s, b.w), n1 - s);     // out col 2L+65
}

__device__ __forceinline__ void do_row(const float* __restrict__ buf, int i,
                                       float* __restrict__ smo, int bo,
                                       int lane, int j0, bool lastlane, float s) {
    const float* r0p = buf + (size_t)(2 * i) * Wd;
    float cmA[4], cmB[4], cmC[4];
    cm_row(r0p,          lane, s, cmA);
    cm_row(r0p + Wd,     lane, s, cmB);
    cm_row(r0p + 2 * Wd, lane, s, cmC);

    float o0 = fmaxf(fmaxf(cmA[0] - s, cmB[0]), cmC[0] - s);
    float o1 = fmaxf(fmaxf(cmA[1] - s, cmB[1]), cmC[1] - s);
    float o2 = fmaxf(fmaxf(cmA[2] - s, cmB[2]), cmC[2] - s);
    float o3 = fmaxf(fmaxf(cmA[3] - s, cmB[3]), cmC[3] - s);

    float* orow = smo + bo + i * OWd;
    orow[j0]      = o0;
    orow[j0 + 1]  = o1;
    orow[j0 + 64] = o2;
    if (!lastlane) orow[j0 + 65] = o3;
}

__global__ void __launch_bounds__(256)
parabolic_pool2d_kernel(const float* __restrict__ f,
                        const float* __restrict__ t,
                        float* __restrict__ out) {
    __shared__ __align__(128) float smi[33 * Wd];   // 33 input rows (33792 B)
    __shared__ __align__(16)  float smo[OUTBUF];    // staged output (8160 B)
    __shared__ __align__(8) unsigned long long mbar[2];

    int bid  = blockIdx.x;
    int img  = bid >> 3;                 // image = b*128 + c
    int tile = bid & 7;                  // 16-output-row tile within image
    int i0 = tile << 4;
    int nout = min(16, OHd - i0);        // 16, or 15 for tile 7
    int nin  = 2 * nout + 1;             // 33 or 31 input rows
    int bytesA = 17 * (Wd * 4);
    int bytesB = (nin - 17) * (Wd * 4);

    const float* src = f + (size_t)img * (256 * Wd) + (size_t)(i0 << 1) * Wd;

    uint32_t smi_a = smem_u32(smi);
    uint32_t mb0 = smem_u32(&mbar[0]);
    uint32_t mb1 = smem_u32(&mbar[1]);

    if (threadIdx.x == 0) {
        asm volatile("mbarrier.init.shared.b64 [%0], 1;" :: "r"(mb0) : "memory");
        asm volatile("mbarrier.init.shared.b64 [%0], 1;" :: "r"(mb1) : "memory");
    }
    __syncthreads();
    if (threadIdx.x == 0) {
        asm volatile("mbarrier.arrive.expect_tx.shared.b64 _, [%0], %1;"
                     :: "r"(mb0), "r"(bytesA) : "memory");
        asm volatile("cp.async.bulk.shared::cta.global.mbarrier::complete_tx::bytes"
                     " [%0], [%1], %2, [%3];"
                     :: "r"(smi_a), "l"(src), "r"(bytesA), "r"(mb0) : "memory");
        asm volatile("mbarrier.arrive.expect_tx.shared.b64 _, [%0], %1;"
                     :: "r"(mb1), "r"(bytesB) : "memory");
        asm volatile("cp.async.bulk.shared::cta.global.mbarrier::complete_tx::bytes"
                     " [%0], [%1], %2, [%3];"
                     :: "r"(smi_a + 17 * Wd * 4), "l"(src + 17 * Wd),
                        "r"(bytesB), "r"(mb1) : "memory");
    }

    // output tile: gmem float index dst_f, contiguous nout*127 floats
    size_t dst_f = (size_t)img * (OHd * OWd) + (size_t)i0 * OWd;
    int bo = (int)(dst_f & 3);           // smem shift so smem==gmem (mod 16B)
    int total_f = nout * OWd;            // 2032 or 1905
    int head = (4 - bo) & 3;
    int middle = (total_f - head) & ~3;  // multiple of 4 floats (16B)
    int tailn = total_f - head - middle; // 0..3

    float s = 0.5f * __ldg(t + (img & 127));
    int tid  = threadIdx.x;
    int w    = tid >> 5;
    int lane = tid & 31;
    int j0   = 2 * lane;
    bool lastlane = (lane == 31);

    // phase 1: output row w (inputs <= 16, chunk A)
    mbar_wait(mb0, 0);
    do_row(smi, w, smo, bo, lane, j0, lastlane, s);

    // phase 2: output row w+8 (inputs 16..32, chunk B)
    mbar_wait(mb1, 0);
    int i = w + 8;
    if (i < nout)
        do_row(smi, i, smo, bo, lane, j0, lastlane, s);

    __syncthreads();                     // all results staged in smo

    float* gout = out + dst_f;
    if (tid < head)  gout[tid] = smo[bo + tid];
    if (tid < tailn) gout[head + middle + tid] = smo[bo + head + middle + tid];
    if (tid == 0) {
        asm volatile("fence.proxy.async.shared::cta;" ::: "memory");
        uint32_t ssrc = smem_u32(smo) + 4 * (bo + head);   // 16B aligned
        const float* gdst = gout + head;                    // 16B aligned
        asm volatile("cp.async.bulk.global.shared::cta.bulk_group [%0], [%1], %2;"
                     :: "l"(gdst), "r"(ssrc), "r"(middle * 4) : "memory");
        asm volatile("cp.async.bulk.commit_group;" ::: "memory");
        asm volatile("cp.async.bulk.wait_group 0;" ::: "memory");
    }
}

extern "C" void kernel_launch(void* const* d_in, const int* in_sizes, int n_in,
                              void* d_out, int out_size) {
    const float* f = (const float*)d_in[0];   // [16,128,256,256] fp32
    const float* t = (const float*)d_in[1];   // [128] fp32
    float* out = (float*)d_out;               // [16,128,127,127] fp32
    // 2048 images * 8 tiles = 16384 blocks, 256 threads each
    parabolic_pool2d_kernel<<<16384, 256>>>(f, t, out);
}